// round 14
// baseline (speedup 1.0000x reference)
#include <cuda_runtime.h>
#include <math.h>
#include <stdint.h>

// ---------------- problem constants ----------------
#define BB 2
#define LL 2048
#define DD 768
#define KK 12
#define KQn 6
#define MM 4
#define HH 64
#define MEMn 768
#define EXPn 192
#define DSWn 384
#define LATn 192
#define BL 4096            // B*L
#define ZC 780             // MEM + K
#define NCH2 64            // scan chunks
#define LC2 32             // chunk length (warp-sized)

// GEMM smem staging geometry (floats)
#define ASZ (128 * 20)
#define BSZ (16 * 136)
#define NSTAGE 5
#define SMEM_BYTES ((NSTAGE * (ASZ + BSZ)) * 4)

// ---------------- scratch (device globals, no allocs) ----------------
__device__ float g_z0[(size_t)BL * ZC];
__device__ float g_qt[(size_t)BL * 3072];     // transposed q: [(b*3072+col)*LL + t]
__device__ float g_gatelin[(size_t)BL * KK];
__device__ float g_lat[(size_t)BL * LATn];
__device__ float g_ydir[(size_t)BL * 4608];
__device__ float g_kval[(size_t)BB * KK * HH * LL];
__device__ float g_pw[(size_t)BB * KK * LL];
__device__ float g_theta[KK * HH * MM];
__device__ float g_wint[KK * HH * MM];
__device__ float g_slope[KK];
__device__ float g_csum[(size_t)BB * KK * HH * MM * 2 * NCH2];
__device__ float g_coff[(size_t)BB * KK * HH * MM * 2 * NCH2];
__device__ float g_dsum[(size_t)BB * KK * NCH2];
__device__ float g_doff[(size_t)BB * KK * NCH2];
__device__ float g_wcat[(size_t)KK * 128 * DSWn];
__device__ float g_A[(size_t)KK * BL * 128];
__device__ float g_yspec[(size_t)KK * BL * DSWn];
__device__ float g_yfin[(size_t)BL * 2304];
// pre-rounded (tf32-valued fp32) GEMM inputs
__device__ float g_xr[(size_t)BL * DD];
__device__ float g_xt[(size_t)BB * DD * LL];   // x transposed per b: [(b*768+kk)*2048+t]
__device__ float g_wqt[(size_t)3072 * DD];     // Wq transposed: [col][kk]
__device__ float g_wmemr[(size_t)DD * ZC];
__device__ float g_sdr[(size_t)DD * LATn];
__device__ float g_sur[(size_t)LATn * 4608];
__device__ float g_owr[(size_t)2304 * DD];

__device__ __forceinline__ float softplusf(float x) {
    return (x > 20.0f) ? x : log1pf(__expf(x));
}

__device__ __forceinline__ float to_tf32(float x) {
    uint32_t u;
    asm("cvt.rna.tf32.f32 %0, %1;" : "=r"(u) : "f"(x));
    return __uint_as_float(u);
}

__device__ __forceinline__ void cp_async16(uint32_t saddr, const void* gptr, int src_bytes) {
    asm volatile("cp.async.cg.shared.global [%0], [%1], 16, %2;"
                 :: "r"(saddr), "l"(gptr), "r"(src_bytes));
}

// ---------------- round x (normal layout) ----------------
__global__ void round_x_kernel(const float* __restrict__ x) {
    int i = blockIdx.x * 256 + threadIdx.x;
    if (i >= BL * DD / 4) return;
    float4 v = ((const float4*)x)[i];
    v.x = to_tf32(v.x); v.y = to_tf32(v.y); v.z = to_tf32(v.z); v.w = to_tf32(v.w);
    ((float4*)g_xr)[i] = v;
}

// ---------------- transpose+round x: [(b*2048+t)][kk] -> [(b*768+kk)][t] --
__global__ void txx_kernel(const float* __restrict__ x) {
    __shared__ float tile[32][33];
    int kb = blockIdx.x * 32;      // kk base
    int tb = blockIdx.y * 32;      // t base
    int b = blockIdx.z;
#pragma unroll
    for (int i = 0; i < 4; i++) {
        int t = tb + threadIdx.y + i * 8;
        tile[threadIdx.y + i * 8][threadIdx.x] =
            x[((size_t)(b * LL + t)) * DD + kb + threadIdx.x];
    }
    __syncthreads();
#pragma unroll
    for (int i = 0; i < 4; i++) {
        int kk = kb + threadIdx.y + i * 8;
        g_xt[((size_t)(b * DD + kk)) * LL + tb + threadIdx.x] =
            to_tf32(tile[threadIdx.x][threadIdx.y + i * 8]);
    }
}

// ---------------- transpose+round Wq: [kk][col] -> [col][kk] --------------
__global__ void txq_kernel(const float* __restrict__ wq) {
    __shared__ float tile[32][33];
    int cb = blockIdx.x * 32;      // col base
    int kb = blockIdx.y * 32;      // kk base
#pragma unroll
    for (int i = 0; i < 4; i++) {
        int kk = kb + threadIdx.y + i * 8;
        tile[threadIdx.y + i * 8][threadIdx.x] = wq[(size_t)kk * 3072 + cb + threadIdx.x];
    }
    __syncthreads();
#pragma unroll
    for (int i = 0; i < 4; i++) {
        int col = cb + threadIdx.y + i * 8;
        g_wqt[(size_t)col * DD + kb + threadIdx.x] =
            to_tf32(tile[threadIdx.x][threadIdx.y + i * 8]);
    }
}

// ---------------- tf32 pre-round, part 2: remaining weights ---------------
#define S1 (DD * ZC / 4)
#define S3 (DD * LATn / 4)
#define S4 (LATn * 4608 / 4)
#define S5 (2304 * DD / 4)
#define RT2 (S1 + S3 + S4 + S5)
__global__ void round_p2_kernel(const float* __restrict__ wm, const float* __restrict__ sd,
                                const float* __restrict__ su, const float* __restrict__ ow) {
    int i = blockIdx.x * 256 + threadIdx.x;
    if (i >= RT2) return;
    const float4* src;
    float4* dst;
    if (i < S1) { src = (const float4*)wm + i; dst = (float4*)g_wmemr + i; }
    else if (i < S1 + S3) { int j = i - S1; src = (const float4*)sd + j; dst = (float4*)g_sdr + j; }
    else if (i < S1 + S3 + S4) { int j = i - S1 - S3; src = (const float4*)su + j; dst = (float4*)g_sur + j; }
    else { int j = i - S1 - S3 - S4; src = (const float4*)ow + j; dst = (float4*)g_owr + j; }
    float4 v = *src;
    v.x = to_tf32(v.x); v.y = to_tf32(v.y); v.z = to_tf32(v.z); v.w = to_tf32(v.w);
    *dst = v;
}

// ---------------- precompute theta / w_int / slopes ----------------
__global__ void precompute_kernel(const float* __restrict__ theta_raw,
                                  const float* __restrict__ decay) {
    int tid = blockIdx.x * blockDim.x + threadIdx.x;
    if (tid < KK * HH) {
        float ta[MM];
        float run = 0.0f;
#pragma unroll
        for (int m = 0; m < MM; m++) {
            run += softplusf(theta_raw[tid * MM + m]) + 1e-4f;
            ta[m] = run;
        }
        float total = ta[MM - 1];
        float sc = 2.999f / total;
        float dth[MM - 1];
#pragma unroll
        for (int i = 0; i < MM - 1; i++) dth[i] = (ta[i + 1] - ta[i]) * sc;
#pragma unroll
        for (int m = 0; m < MM; m++) g_theta[tid * MM + m] = 0.001f + ta[m] * sc;
        g_wint[tid * MM + 0] = dth[0] * 0.5f;
        g_wint[tid * MM + 1] = 0.5f * (dth[0] + dth[1]);
        g_wint[tid * MM + 2] = 0.5f * (dth[1] + dth[2]);
        g_wint[tid * MM + 3] = dth[2] * 0.5f;
    }
    if (tid < KK) g_slope[tid] = softplusf(decay[tid]);
}

// ---------------- concat [W_re ; W_im] per k (rounded: feeds GEMM) --------
__global__ void wcat_kernel(const float* __restrict__ Wre, const float* __restrict__ Wim) {
    int idx = blockIdx.x * 256 + threadIdx.x;
    if (idx >= KK * 128 * DSWn) return;
    int n = idx % DSWn;
    int r = (idx / DSWn) % 128;
    int k = idx / (128 * DSWn);
    float v = (r < HH) ? Wre[((size_t)k * HH + r) * DSWn + n]
                       : Wim[((size_t)k * HH + (r - HH)) * DSWn + n];
    g_wcat[idx] = to_tf32(v);
}

// ---------------- tf32 tensor GEMM, 128x128 tile, 5-stage cp.async -------
__global__ void __launch_bounds__(256, 2) tgemm_kernel(
    const float* __restrict__ A, const float* __restrict__ Bm, float* __restrict__ C,
    int Nn, int Kk, size_t sA, size_t sB, size_t sC, int roundOut) {
    A += (size_t)blockIdx.z * sA;
    Bm += (size_t)blockIdx.z * sB;
    C += (size_t)blockIdx.z * sC;

    extern __shared__ float sm[];
    const uint32_t smu = (uint32_t)__cvta_generic_to_shared(sm);

    const int tid = threadIdx.x;
    const int lane = tid & 31;
    const int wid = tid >> 5;
    const int wm = wid >> 2;
    const int wn = wid & 3;
    const int g = lane >> 2;
    const int tc4 = lane & 3;

    const int rowBase = blockIdx.y * 128;
    const int colBase = blockIdx.x * 128;

    float acc[4][4][4];
#pragma unroll
    for (int i = 0; i < 4; i++)
#pragma unroll
        for (int j = 0; j < 4; j++)
#pragma unroll
            for (int r = 0; r < 4; r++) acc[i][j][r] = 0.0f;

    const int KT = Kk >> 4;

#define ISSUE_STAGE(st, k0)                                                     \
    {                                                                           \
        uint32_t abase = smu + (uint32_t)((st) * ASZ) * 4;                      \
        uint32_t bbase = smu + (uint32_t)(NSTAGE * ASZ + (st) * BSZ) * 4;       \
        _Pragma("unroll")                                                       \
        for (int i = 0; i < 2; i++) {                                           \
            int row = ((tid * 2 + i) >> 2);                                     \
            int kc = (tid * 2 + i) & 3;                                         \
            uint32_t sa = abase + (uint32_t)(row * 20 + kc * 4) * 4;            \
            const float* gp = A + (size_t)(rowBase + row) * Kk + (k0) + kc * 4; \
            cp_async16(sa, gp, 16);                                             \
        }                                                                       \
        _Pragma("unroll")                                                       \
        for (int i = 0; i < 2; i++) {                                           \
            int row = ((tid * 2 + i) >> 5);                                     \
            int nc = (tid * 2 + i) & 31;                                        \
            int cc = colBase + nc * 4;                                          \
            uint32_t sb = bbase + (uint32_t)(row * 136 + nc * 4) * 4;           \
            const float* rowp = Bm + (size_t)((k0) + row) * Nn;                 \
            int sz = (Nn - cc) * 4;                                             \
            sz = sz < 0 ? 0 : (sz > 16 ? 16 : sz);                              \
            const float* gp = (cc < Nn) ? (rowp + cc) : rowp;                   \
            cp_async16(sb, gp, sz);                                             \
        }                                                                       \
        asm volatile("cp.async.commit_group;");                                 \
    }

#pragma unroll
    for (int s = 0; s < NSTAGE - 1; s++) {
        if (s < KT) { ISSUE_STAGE(s, s << 4); }
        else { asm volatile("cp.async.commit_group;"); }
    }

    int cur = 0;
    for (int kt = 0; kt < KT; kt++) {
        asm volatile("cp.async.wait_group %0;" :: "n"(NSTAGE - 2));
        __syncthreads();
        if (kt + NSTAGE - 1 < KT) {
            int st = (kt + NSTAGE - 1) % NSTAGE;
            ISSUE_STAGE(st, (kt + NSTAGE - 1) << 4);
        } else {
            asm volatile("cp.async.commit_group;");
        }
        const float* Ab = sm + cur * ASZ;
        const float* Bb = sm + NSTAGE * ASZ + cur * BSZ;
#pragma unroll
        for (int ks = 0; ks < 2; ks++) {
            const int kf = ks * 8 + tc4;
            uint32_t af[4][4];
#pragma unroll
            for (int mt = 0; mt < 4; mt++) {
                int m0 = wm * 64 + mt * 16 + g;
                af[mt][0] = __float_as_uint(Ab[m0 * 20 + kf]);
                af[mt][1] = __float_as_uint(Ab[(m0 + 8) * 20 + kf]);
                af[mt][2] = __float_as_uint(Ab[m0 * 20 + kf + 4]);
                af[mt][3] = __float_as_uint(Ab[(m0 + 8) * 20 + kf + 4]);
            }
            const float* Bk0 = Bb + kf * 136;
            const float* Bk1 = Bb + (kf + 4) * 136;
            uint32_t bf[4][2];
#pragma unroll
            for (int nt = 0; nt < 4; nt++) {
                int n0 = wn * 32 + nt * 8 + g;
                bf[nt][0] = __float_as_uint(Bk0[n0]);
                bf[nt][1] = __float_as_uint(Bk1[n0]);
            }
#pragma unroll
            for (int mt = 0; mt < 4; mt++)
#pragma unroll
                for (int nt = 0; nt < 4; nt++) {
                    asm volatile(
                        "mma.sync.aligned.m16n8k8.row.col.f32.tf32.tf32.f32 "
                        "{%0,%1,%2,%3}, {%4,%5,%6,%7}, {%8,%9}, {%0,%1,%2,%3};"
                        : "+f"(acc[mt][nt][0]), "+f"(acc[mt][nt][1]),
                          "+f"(acc[mt][nt][2]), "+f"(acc[mt][nt][3])
                        : "r"(af[mt][0]), "r"(af[mt][1]), "r"(af[mt][2]), "r"(af[mt][3]),
                          "r"(bf[nt][0]), "r"(bf[nt][1]));
                }
        }
        cur = (cur + 1) % NSTAGE;
    }
#undef ISSUE_STAGE

#pragma unroll
    for (int mt = 0; mt < 4; mt++) {
        int r0 = rowBase + wm * 64 + mt * 16 + g;
#pragma unroll
        for (int nt = 0; nt < 4; nt++) {
            int cc = colBase + wn * 32 + nt * 8 + tc4 * 2;
            float c0 = acc[mt][nt][0], c1 = acc[mt][nt][1];
            float c2 = acc[mt][nt][2], c3 = acc[mt][nt][3];
            if (roundOut) {
                c0 = to_tf32(c0); c1 = to_tf32(c1); c2 = to_tf32(c2); c3 = to_tf32(c3);
            }
            if (cc + 1 < Nn) {
                *(float2*)(C + (size_t)r0 * Nn + cc) = make_float2(c0, c1);
                *(float2*)(C + (size_t)(r0 + 8) * Nn + cc) = make_float2(c2, c3);
            } else if (cc < Nn) {
                C[(size_t)r0 * Nn + cc] = c0;
                C[(size_t)(r0 + 8) * Nn + cc] = c2;
            }
        }
    }
}

// ---------------- dedicated gate GEMM: N=12, warp-per-row ----------------
__global__ void __launch_bounds__(256) gate_kernel(const float* __restrict__ x,
                                                   const float* __restrict__ gW) {
    int row = blockIdx.x * 8 + (threadIdx.x >> 5);
    int lane = threadIdx.x & 31;
    const float* xr = x + (size_t)row * DD;
    float acc[KK];
#pragma unroll
    for (int j = 0; j < KK; j++) acc[j] = 0.0f;
    for (int k = lane; k < DD; k += 32) {
        float xv = xr[k];
        const float* gp = gW + (size_t)k * KK;
#pragma unroll
        for (int j = 0; j < KK; j++) acc[j] += xv * gp[j];
    }
#pragma unroll
    for (int j = 0; j < KK; j++) {
        float v = acc[j];
#pragma unroll
        for (int d = 16; d > 0; d >>= 1) v += __shfl_down_sync(0xffffffffu, v, d);
        if (lane == 0) g_gatelin[(size_t)row * KK + j] = v;
    }
}

// ---------------- depthwise causal conv + transpose to (b,k,h,t) ----------
__global__ void conv_kernel(const float* __restrict__ ck, const float* __restrict__ sscale) {
    __shared__ float tile[32][33];
    int b = blockIdx.z;
    int cBase = blockIdx.x * 32;
    int tBase = blockIdx.y * 32;
    int c = cBase + threadIdx.x;
    float kc[4] = {0.f, 0.f, 0.f, 0.f};
    if (c < ZC) {
#pragma unroll
        for (int j = 0; j < 4; j++) kc[j] = ck[j * ZC + c];
    }
#pragma unroll
    for (int i = 0; i < 4; i++) {
        int t = tBase + threadIdx.y + i * 8;
        float val = 0.0f;
        if (c < ZC) {
#pragma unroll
            for (int j = 0; j < 4; j++) {
                int tt = t - 3 + j;
                if (tt >= 0) val += g_z0[((size_t)(b * LL + tt)) * ZC + c] * kc[j];
            }
        }
        tile[threadIdx.x][threadIdx.y + i * 8] = val;
    }
    __syncthreads();
    int tid = threadIdx.y * 32 + threadIdx.x;
#pragma unroll
    for (int i = 0; i < 4; i++) {
        int idx = tid + i * 256;
        int cl = idx >> 5, tl = idx & 31;
        int cc = cBase + cl;
        int t = tBase + tl;
        if (cc < MEMn) {
            int k = cc >> 6, h = cc & 63;
            g_kval[(((size_t)b * KK + k) * HH + h) * LL + t] = tile[cl][tl];
        } else if (cc < ZC) {
            int k = cc - MEMn;
            float v = tile[cl][tl];
            float lp = fminf(fmaxf(sscale[k] * v, -20.0f), 20.0f);
            float ltw = -g_slope[k] * (float)(LL - 1 - t);
            g_pw[((size_t)b * KK + k) * LL + t] = __expf(lp + ltw);
        }
    }
}

// ---------------- per-chunk partial sums (warp-autonomous, chunk=32) ------
__global__ void __launch_bounds__(256) chunksum_kernel(const float* __restrict__ tscale) {
    int bk = blockIdx.z;
    int k = bk % KK;
    int h = blockIdx.y;
    int w = threadIdx.x >> 5, lane = threadIdx.x & 31;
    int chunk = blockIdx.x * 8 + w;
    int t = chunk * LC2 + lane;

    float pw = g_pw[(size_t)bk * LL + t];
    float kv = g_kval[(((size_t)bk) * HH + h) * LL + t];
    float kvw = kv * pw;
    float tanhv = tanhf(tscale[k] * kv);
    int thb = (k * HH + h) * MM;
    float vals[9];
#pragma unroll
    for (int m = 0; m < MM; m++) {
        float s, c2;
        __sincosf(tanhv * g_theta[thb + m], &s, &c2);
        vals[2 * m] = kvw * c2;
        vals[2 * m + 1] = kvw * s;
    }
    vals[8] = pw;

#pragma unroll
    for (int j = 0; j < 9; j++) {
        float x = vals[j];
#pragma unroll
        for (int d = 16; d > 0; d >>= 1) x += __shfl_xor_sync(0xffffffffu, x, d);
        vals[j] = x;
    }
    if (lane == 0) {
#pragma unroll
        for (int j = 0; j < 8; j++) {
            int m = j >> 1, ri = j & 1;
            size_t ch = (((size_t)bk * HH + h) * MM + m) * 2 + ri;
            g_csum[ch * NCH2 + chunk] = vals[j];
        }
        if (h == 0) g_dsum[(size_t)bk * NCH2 + chunk] = vals[8];
    }
}

// ---------------- exclusive scan of chunk sums (phase 2) ----------------
__global__ void scanoff_kernel() {
    int idx = blockIdx.x * 256 + threadIdx.x;
    const int NRI = BB * KK * HH * MM * 2;
    if (idx < NRI) {
        float run = 0.0f;
#pragma unroll 8
        for (int c = 0; c < NCH2; c++) {
            float x = g_csum[(size_t)idx * NCH2 + c];
            g_coff[(size_t)idx * NCH2 + c] = run;
            run += x;
        }
    } else if (idx < NRI + BB * KK) {
        int d = idx - NRI;
        float run = 0.0f;
#pragma unroll 8
        for (int c = 0; c < NCH2; c++) {
            float x = g_dsum[(size_t)d * NCH2 + c];
            g_doff[(size_t)d * NCH2 + c] = run;
            run += x;
        }
    }
}

// ---------------- fused in-chunk scan + q-combine (per-b, h-split) --------
__global__ void __launch_bounds__(256) phase3_kernel(const float* __restrict__ tscale,
                                                     const float* __restrict__ nscale,
                                                     int b) {
    __shared__ float tile[8][32][33];
    int hq = blockIdx.z;
    int k = blockIdx.y;
    int w = threadIdx.x >> 5, lane = threadIdx.x & 31;
    int chunk = blockIdx.x * 8 + w;
    int t = chunk * LC2 + lane;
    int bk = b * KK + k;

    float pw = g_pw[(size_t)bk * LL + t];
    float x = pw;
#pragma unroll
    for (int d = 1; d < 32; d <<= 1) {
        float n = __shfl_up_sync(0xffffffffu, x, d);
        if (lane >= d) x += n;
    }
    float den = g_doff[(size_t)bk * NCH2 + chunk] + x;
    float invden = 1.0f / fmaxf(den, 1e-4f);

    int kq = k >> 1;
    const float* qbase = g_qt + ((size_t)(b * 3072 + kq * 512)) * LL + t;
    float ts = tscale[k];
    size_t kvbase = ((size_t)bk * HH) * LL + t;
    size_t chb_base = ((size_t)bk * HH) * MM;
    int thb_base = (k * HH) * MM;

    const int h0 = hq * 16;
    for (int hl = 0; hl < 16; hl++) {
        int h = h0 + hl;
        float kv = g_kval[kvbase + (size_t)h * LL];
        float kvw = kv * pw;
        float tanhv = tanhf(ts * kv);
        const float* qp = qbase + (size_t)(h * 8) * LL;
        float qv[8];
#pragma unroll
        for (int j = 0; j < 8; j++) qv[j] = qp[(size_t)j * LL];
        int thb = thb_base + h * MM;
        size_t chb = chb_base + (size_t)h * MM;
        float v[8];
#pragma unroll
        for (int m = 0; m < MM; m++) {
            float s, c2;
            __sincosf(tanhv * g_theta[thb + m], &s, &c2);
            v[2 * m] = kvw * c2;
            v[2 * m + 1] = kvw * s;
        }
#pragma unroll
        for (int j = 0; j < 8; j++) {
            float y = v[j];
#pragma unroll
            for (int d = 1; d < 32; d <<= 1) {
                float n = __shfl_up_sync(0xffffffffu, y, d);
                if (lane >= d) y += n;
            }
            v[j] = y;
        }
        float accre = 0.0f, accim = 0.0f;
#pragma unroll
        for (int m = 0; m < MM; m++) {
            float offre = g_coff[((chb + m) * 2 + 0) * NCH2 + chunk];
            float offim = g_coff[((chb + m) * 2 + 1) * NCH2 + chunk];
            float sre = (offre + v[2 * m]) * invden;
            float sim = (offim + v[2 * m + 1]) * invden;
            float wg = g_wint[thb + m];
            float qr = qv[2 * m], qi = qv[2 * m + 1];
            accre += (sre * qr + sim * qi) * wg;
            accim += (sim * qr - sre * qi) * wg;
        }
        float ns = nscale[k * HH + h];
        tile[w][lane][hl] = to_tf32(accre * ns);
        tile[w][lane][16 + hl] = to_tf32(accim * ns);
    }
    __syncwarp();
    size_t Abase = ((size_t)k * BL + (size_t)b * LL + (size_t)chunk * LC2) * 128;
    int hh = (lane < 16) ? (h0 + lane) : (64 + h0 + (lane - 16));
    for (int r = 0; r < 32; r++) {
        g_A[Abase + (size_t)r * 128 + hh] = tile[w][r][lane];
    }
}

// ---------------- gate/highway/silu epilogue (per-b rows) -----------------
__global__ void combine2_kernel(const float* __restrict__ gate_b,
                                const float* __restrict__ hscale, int row0) {
    int idx = blockIdx.x * 256 + threadIdx.x;
    if (idx >= (BL / 2) * 2304) return;
    int row = row0 + idx / 2304, n = idx % 2304;
    int k = n / EXPn, e = n % EXPn;
    size_t sb = ((size_t)k * BL + row) * DSWn;
    float sv = g_yspec[sb + e];
    float sg = g_yspec[sb + EXPn + e];
    size_t db = (size_t)row * 4608 + (size_t)k * DSWn;
    float dv = g_ydir[db + e];
    float dg = g_ydir[db + EXPn + e];
    float gate = 1.0f / (1.0f + __expf(-(g_gatelin[(size_t)row * KK + k] + gate_b[k])));
    float hs = hscale[k];
    float val = sv * gate + dv * hs;
    float gt = sg * gate + dg * hs;
    g_yfin[(size_t)row * 2304 + n] = to_tf32(val * gt / (1.0f + __expf(-gt)));
}

// ---------------- host launcher (multi-stream fork/join, capturable) ------
extern "C" void kernel_launch(void* const* d_in, const int* in_sizes, int n_in,
                              void* d_out, int out_size) {
    const float* x = (const float*)d_in[0];
    const float* W_mem = (const float*)d_in[1];
    const float* conv_k = (const float*)d_in[2];
    const float* W_q = (const float*)d_in[3];
    const float* theta_raw = (const float*)d_in[4];
    const float* decay = (const float*)d_in[5];
    const float* sscale = (const float*)d_in[6];
    const float* tscale = (const float*)d_in[7];
    const float* W_re = (const float*)d_in[8];
    const float* W_im = (const float*)d_in[9];
    const float* nscale = (const float*)d_in[10];
    const float* gate_W = (const float*)d_in[11];
    const float* gate_b = (const float*)d_in[12];
    const float* skip_down = (const float*)d_in[13];
    const float* skip_up = (const float*)d_in[14];
    const float* hscale = (const float*)d_in[15];
    const float* out_W = (const float*)d_in[16];

    float *z0, *qt, *lat, *ydir, *A, *wcat, *yspec, *yfin;
    float *xr, *xt, *wqt, *wmemr, *sdr, *sur, *owr;
    cudaGetSymbolAddress((void**)&z0, g_z0);
    cudaGetSymbolAddress((void**)&qt, g_qt);
    cudaGetSymbolAddress((void**)&lat, g_lat);
    cudaGetSymbolAddress((void**)&ydir, g_ydir);
    cudaGetSymbolAddress((void**)&A, g_A);
    cudaGetSymbolAddress((void**)&wcat, g_wcat);
    cudaGetSymbolAddress((void**)&yspec, g_yspec);
    cudaGetSymbolAddress((void**)&yfin, g_yfin);
    cudaGetSymbolAddress((void**)&xr, g_xr);
    cudaGetSymbolAddress((void**)&xt, g_xt);
    cudaGetSymbolAddress((void**)&wqt, g_wqt);
    cudaGetSymbolAddress((void**)&wmemr, g_wmemr);
    cudaGetSymbolAddress((void**)&sdr, g_sdr);
    cudaGetSymbolAddress((void**)&sur, g_sur);
    cudaGetSymbolAddress((void**)&owr, g_owr);

    static cudaStream_t s1 = 0, s2 = 0, s3 = 0;
    static cudaEvent_t eR1 = 0, eR2 = 0, eQT0 = 0, eQT1 = 0, eDir = 0, eP0 = 0, eTail = 0;
    static int init_done = 0;
    if (!init_done) {
        cudaFuncSetAttribute(tgemm_kernel, cudaFuncAttributeMaxDynamicSharedMemorySize,
                             SMEM_BYTES);
        cudaStreamCreateWithFlags(&s1, cudaStreamNonBlocking);
        cudaStreamCreateWithFlags(&s2, cudaStreamNonBlocking);
        cudaStreamCreateWithFlags(&s3, cudaStreamNonBlocking);
        cudaEventCreateWithFlags(&eR1, cudaEventDisableTiming);
        cudaEventCreateWithFlags(&eR2, cudaEventDisableTiming);
        cudaEventCreateWithFlags(&eQT0, cudaEventDisableTiming);
        cudaEventCreateWithFlags(&eQT1, cudaEventDisableTiming);
        cudaEventCreateWithFlags(&eDir, cudaEventDisableTiming);
        cudaEventCreateWithFlags(&eP0, cudaEventDisableTiming);
        cudaEventCreateWithFlags(&eTail, cudaEventDisableTiming);
        init_done = 1;
    }

    // ---- prologue: x/Wq transposes so qt GEMMs start ASAP ----
    round_x_kernel<<<(BL * DD / 4 + 255) / 256, 256>>>(x);
    txq_kernel<<<dim3(96, 24), dim3(32, 8)>>>(W_q);
    txx_kernel<<<dim3(24, 64, BB), dim3(32, 8)>>>(x);
    cudaEventRecord(eR1, 0);
    cudaStreamWaitEvent(s1, eR1, 0);
    cudaStreamWaitEvent(s3, eR1, 0);

    // ---- side streams s1/s3: qt GEMM per batch (writes transposed q) ----
    // qt_b [3072 x 2048] = wqt [3072 x 768] @ xt_b [768 x 2048]
    tgemm_kernel<<<dim3(16, 24, 1), 256, SMEM_BYTES, s1>>>(
        wqt, xt, qt, LL, DD, 0, 0, 0, 0);
    cudaEventRecord(eQT0, s1);
    tgemm_kernel<<<dim3(16, 24, 1), 256, SMEM_BYTES, s3>>>(
        wqt, xt + (size_t)DD * LL, qt + (size_t)3072 * LL, LL, DD, 0, 0, 0, 0);
    cudaEventRecord(eQT1, s3);

    // ---- rest of prologue on main stream ----
    round_p2_kernel<<<(RT2 + 255) / 256, 256>>>(W_mem, skip_down, skip_up, out_W);
    precompute_kernel<<<3, 256>>>(theta_raw, decay);
    wcat_kernel<<<(KK * 128 * DSWn + 255) / 256, 256>>>(W_re, W_im);
    cudaEventRecord(eR2, 0);
    cudaStreamWaitEvent(s2, eR2, 0);

    // ---- side stream s2: skip path + gate ----
    tgemm_kernel<<<dim3(2, 32, 1), 256, SMEM_BYTES, s2>>>(xr, sdr, lat, LATn, DD, 0, 0, 0, 1);
    tgemm_kernel<<<dim3(36, 32, 1), 256, SMEM_BYTES, s2>>>(lat, sur, ydir, 4608, LATn, 0, 0, 0, 0);
    gate_kernel<<<BL / 8, 256, 0, s2>>>(x, gate_W);
    cudaEventRecord(eDir, s2);

    // ---- main critical chain ----
    tgemm_kernel<<<dim3(7, 32, 1), 256, SMEM_BYTES>>>(xr, wmemr, z0, ZC, DD, 0, 0, 0, 0);
    conv_kernel<<<dim3(25, 64, BB), dim3(32, 8)>>>(conv_k, sscale);
    chunksum_kernel<<<dim3(8, HH, BB * KK), 256>>>(tscale);
    scanoff_kernel<<<(BB * KK * HH * MM * 2 + BB * KK + 255) / 256, 256>>>();

    // ---- tail pipeline, split by batch b ----
    cudaStreamWaitEvent(0, eQT0, 0);
    phase3_kernel<<<dim3(8, KK, 4), 256>>>(tscale, nscale, 0);
    cudaEventRecord(eP0, 0);

    cudaStreamWaitEvent(0, eQT1, 0);
    phase3_kernel<<<dim3(8, KK, 4), 256>>>(tscale, nscale, 1);

    // s1: b=0 tail
    cudaStreamWaitEvent(s1, eP0, 0);
    tgemm_kernel<<<dim3(3, 16, KK), 256, SMEM_BYTES, s1>>>(
        A, wcat, yspec, DSWn, 128,
        (size_t)BL * 128, (size_t)128 * DSWn, (size_t)BL * DSWn, 0);
    cudaStreamWaitEvent(s1, eDir, 0);
    combine2_kernel<<<((size_t)(BL / 2) * 2304 + 255) / 256, 256, 0, s1>>>(gate_b, hscale, 0);
    tgemm_kernel<<<dim3(6, 16, 1), 256, SMEM_BYTES, s1>>>(
        yfin, owr, (float*)d_out, DD, 2304, 0, 0, 0, 0);
    cudaEventRecord(eTail, s1);

    // main: b=1 tail
    tgemm_kernel<<<dim3(3, 16, KK), 256, SMEM_BYTES>>>(
        A + (size_t)LL * 128, wcat, yspec + (size_t)LL * DSWn, DSWn, 128,
        (size_t)BL * 128, (size_t)128 * DSWn, (size_t)BL * DSWn, 0);
    cudaStreamWaitEvent(0, eDir, 0);
    combine2_kernel<<<((size_t)(BL / 2) * 2304 + 255) / 256, 256>>>(gate_b, hscale, LL);
    tgemm_kernel<<<dim3(6, 16, 1), 256, SMEM_BYTES>>>(
        yfin + (size_t)LL * 2304, owr, (float*)d_out + (size_t)LL * DD, DD, 2304, 0, 0, 0, 0);

    cudaStreamWaitEvent(0, eTail, 0);
}

// round 15
// speedup vs baseline: 1.0344x; 1.0344x over previous
#include <cuda_runtime.h>
#include <math.h>
#include <stdint.h>

// ---------------- problem constants ----------------
#define BB 2
#define LL 2048
#define DD 768
#define KK 12
#define KQn 6
#define MM 4
#define HH 64
#define MEMn 768
#define EXPn 192
#define DSWn 384
#define LATn 192
#define BL 4096            // B*L
#define ZC 780             // MEM + K
#define NCH2 64            // scan chunks
#define LC2 32             // chunk length (warp-sized)

// GEMM smem staging geometry (floats)
#define ASZ (128 * 20)
#define BSZ (16 * 136)
#define NSTAGE 5
#define SMEM_BYTES ((NSTAGE * (ASZ + BSZ)) * 4)

// ---------------- scratch (device globals, no allocs) ----------------
__device__ float g_z0[(size_t)BL * ZC];
__device__ float g_q[(size_t)BL * 3072];
__device__ float g_qt[(size_t)BL * 3072];     // transposed q: [(b*3072+col)*LL + t]
__device__ float g_gatelin[(size_t)BL * KK];
__device__ float g_lat[(size_t)BL * LATn];
__device__ float g_ydir[(size_t)BL * 4608];
__device__ float g_kval[(size_t)BB * KK * HH * LL];
__device__ float g_pw[(size_t)BB * KK * LL];
__device__ float g_theta[KK * HH * MM];
__device__ float g_wint[KK * HH * MM];
__device__ float g_slope[KK];
__device__ float g_csum[(size_t)BB * KK * HH * MM * 2 * NCH2];
__device__ float g_coff[(size_t)BB * KK * HH * MM * 2 * NCH2];
__device__ float g_dsum[(size_t)BB * KK * NCH2];
__device__ float g_doff[(size_t)BB * KK * NCH2];
__device__ float g_wcat[(size_t)KK * 128 * DSWn];
__device__ float g_A[(size_t)KK * BL * 128];
__device__ float g_yspec[(size_t)KK * BL * DSWn];
__device__ float g_yfin[(size_t)BL * 2304];
// pre-rounded (tf32-valued fp32) GEMM inputs
__device__ float g_xr[(size_t)BL * DD];
__device__ float g_wmemr[(size_t)DD * ZC];
__device__ float g_wqr[(size_t)DD * 3072];
__device__ float g_sdr[(size_t)DD * LATn];
__device__ float g_sur[(size_t)LATn * 4608];
__device__ float g_owr[(size_t)2304 * DD];

__device__ __forceinline__ float softplusf(float x) {
    return (x > 20.0f) ? x : log1pf(__expf(x));
}

__device__ __forceinline__ float to_tf32(float x) {
    uint32_t u;
    asm("cvt.rna.tf32.f32 %0, %1;" : "=r"(u) : "f"(x));
    return __uint_as_float(u);
}

__device__ __forceinline__ void cp_async16(uint32_t saddr, const void* gptr, int src_bytes) {
    asm volatile("cp.async.cg.shared.global [%0], [%1], 16, %2;"
                 :: "r"(saddr), "l"(gptr), "r"(src_bytes));
}

// ---------------- tf32 pre-round, part 1: x + W_q (feeds q GEMM) ----------
#define S0 (BL * DD / 4)           // x        786432
#define S2 (DD * 3072 / 4)         // W_q      589824
#define RT1 (S0 + S2)
__global__ void round_p1_kernel(const float* __restrict__ x, const float* __restrict__ wq) {
    int i = blockIdx.x * 256 + threadIdx.x;
    if (i >= RT1) return;
    const float4* src;
    float4* dst;
    if (i < S0) { src = (const float4*)x + i; dst = (float4*)g_xr + i; }
    else { int j = i - S0; src = (const float4*)wq + j; dst = (float4*)g_wqr + j; }
    float4 v = *src;
    v.x = to_tf32(v.x); v.y = to_tf32(v.y); v.z = to_tf32(v.z); v.w = to_tf32(v.w);
    *dst = v;
}

// ---------------- tf32 pre-round, part 2: remaining weights ---------------
#define S1 (DD * ZC / 4)           // W_mem    149760
#define S3 (DD * LATn / 4)         // skip_dn   36864
#define S4 (LATn * 4608 / 4)       // skip_up  221184
#define S5 (2304 * DD / 4)         // out_W    442368
#define RT2 (S1 + S3 + S4 + S5)
__global__ void round_p2_kernel(const float* __restrict__ wm, const float* __restrict__ sd,
                                const float* __restrict__ su, const float* __restrict__ ow) {
    int i = blockIdx.x * 256 + threadIdx.x;
    if (i >= RT2) return;
    const float4* src;
    float4* dst;
    if (i < S1) { src = (const float4*)wm + i; dst = (float4*)g_wmemr + i; }
    else if (i < S1 + S3) { int j = i - S1; src = (const float4*)sd + j; dst = (float4*)g_sdr + j; }
    else if (i < S1 + S3 + S4) { int j = i - S1 - S3; src = (const float4*)su + j; dst = (float4*)g_sur + j; }
    else { int j = i - S1 - S3 - S4; src = (const float4*)ow + j; dst = (float4*)g_owr + j; }
    float4 v = *src;
    v.x = to_tf32(v.x); v.y = to_tf32(v.y); v.z = to_tf32(v.z); v.w = to_tf32(v.w);
    *dst = v;
}

// ---------------- q transpose (column half): [BL][3072] -> [(b*3072+c)*LL+t]
__global__ void qt_kernel(int cb0) {
    __shared__ float tile[32][33];
    int cb = cb0 + blockIdx.x * 32;
    int rb = blockIdx.y * 32;
#pragma unroll
    for (int i = 0; i < 4; i++) {
        int r = rb + threadIdx.y + i * 8;
        tile[threadIdx.y + i * 8][threadIdx.x] = g_q[(size_t)r * 3072 + cb + threadIdx.x];
    }
    __syncthreads();
    int b = rb >> 11;
    int tloc = (rb & 2047) + threadIdx.x;
#pragma unroll
    for (int i = 0; i < 4; i++) {
        int col = cb + threadIdx.y + i * 8;
        g_qt[((size_t)(b * 3072 + col)) * LL + tloc] = tile[threadIdx.x][threadIdx.y + i * 8];
    }
}

// ---------------- precompute theta / w_int / slopes ----------------
__global__ void precompute_kernel(const float* __restrict__ theta_raw,
                                  const float* __restrict__ decay) {
    int tid = blockIdx.x * blockDim.x + threadIdx.x;
    if (tid < KK * HH) {
        float ta[MM];
        float run = 0.0f;
#pragma unroll
        for (int m = 0; m < MM; m++) {
            run += softplusf(theta_raw[tid * MM + m]) + 1e-4f;
            ta[m] = run;
        }
        float total = ta[MM - 1];
        float sc = 2.999f / total;
        float dth[MM - 1];
#pragma unroll
        for (int i = 0; i < MM - 1; i++) dth[i] = (ta[i + 1] - ta[i]) * sc;
#pragma unroll
        for (int m = 0; m < MM; m++) g_theta[tid * MM + m] = 0.001f + ta[m] * sc;
        g_wint[tid * MM + 0] = dth[0] * 0.5f;
        g_wint[tid * MM + 1] = 0.5f * (dth[0] + dth[1]);
        g_wint[tid * MM + 2] = 0.5f * (dth[1] + dth[2]);
        g_wint[tid * MM + 3] = dth[2] * 0.5f;
    }
    if (tid < KK) g_slope[tid] = softplusf(decay[tid]);
}

// ---------------- concat [W_re ; W_im] per k (rounded: feeds GEMM) --------
__global__ void wcat_kernel(const float* __restrict__ Wre, const float* __restrict__ Wim) {
    int idx = blockIdx.x * 256 + threadIdx.x;
    if (idx >= KK * 128 * DSWn) return;
    int n = idx % DSWn;
    int r = (idx / DSWn) % 128;
    int k = idx / (128 * DSWn);
    float v = (r < HH) ? Wre[((size_t)k * HH + r) * DSWn + n]
                       : Wim[((size_t)k * HH + (r - HH)) * DSWn + n];
    g_wcat[idx] = to_tf32(v);
}

// ---------------- tf32 tensor GEMM, 128x128 tile, 5-stage cp.async -------
__global__ void __launch_bounds__(256, 2) tgemm_kernel(
    const float* __restrict__ A, const float* __restrict__ Bm, float* __restrict__ C,
    int Nn, int Kk, size_t sA, size_t sB, size_t sC, int roundOut) {
    A += (size_t)blockIdx.z * sA;
    Bm += (size_t)blockIdx.z * sB;
    C += (size_t)blockIdx.z * sC;

    extern __shared__ float sm[];
    const uint32_t smu = (uint32_t)__cvta_generic_to_shared(sm);

    const int tid = threadIdx.x;
    const int lane = tid & 31;
    const int wid = tid >> 5;
    const int wm = wid >> 2;
    const int wn = wid & 3;
    const int g = lane >> 2;
    const int tc4 = lane & 3;

    const int rowBase = blockIdx.y * 128;
    const int colBase = blockIdx.x * 128;

    float acc[4][4][4];
#pragma unroll
    for (int i = 0; i < 4; i++)
#pragma unroll
        for (int j = 0; j < 4; j++)
#pragma unroll
            for (int r = 0; r < 4; r++) acc[i][j][r] = 0.0f;

    const int KT = Kk >> 4;

#define ISSUE_STAGE(st, k0)                                                     \
    {                                                                           \
        uint32_t abase = smu + (uint32_t)((st) * ASZ) * 4;                      \
        uint32_t bbase = smu + (uint32_t)(NSTAGE * ASZ + (st) * BSZ) * 4;       \
        _Pragma("unroll")                                                       \
        for (int i = 0; i < 2; i++) {                                           \
            int row = ((tid * 2 + i) >> 2);                                     \
            int kc = (tid * 2 + i) & 3;                                         \
            uint32_t sa = abase + (uint32_t)(row * 20 + kc * 4) * 4;            \
            const float* gp = A + (size_t)(rowBase + row) * Kk + (k0) + kc * 4; \
            cp_async16(sa, gp, 16);                                             \
        }                                                                       \
        _Pragma("unroll")                                                       \
        for (int i = 0; i < 2; i++) {                                           \
            int row = ((tid * 2 + i) >> 5);                                     \
            int nc = (tid * 2 + i) & 31;                                        \
            int cc = colBase + nc * 4;                                          \
            uint32_t sb = bbase + (uint32_t)(row * 136 + nc * 4) * 4;           \
            const float* rowp = Bm + (size_t)((k0) + row) * Nn;                 \
            int sz = (Nn - cc) * 4;                                             \
            sz = sz < 0 ? 0 : (sz > 16 ? 16 : sz);                              \
            const float* gp = (cc < Nn) ? (rowp + cc) : rowp;                   \
            cp_async16(sb, gp, sz);                                             \
        }                                                                       \
        asm volatile("cp.async.commit_group;");                                 \
    }

#pragma unroll
    for (int s = 0; s < NSTAGE - 1; s++) {
        if (s < KT) { ISSUE_STAGE(s, s << 4); }
        else { asm volatile("cp.async.commit_group;"); }
    }

    int cur = 0;
    for (int kt = 0; kt < KT; kt++) {
        asm volatile("cp.async.wait_group %0;" :: "n"(NSTAGE - 2));
        __syncthreads();
        if (kt + NSTAGE - 1 < KT) {
            int st = (kt + NSTAGE - 1) % NSTAGE;
            ISSUE_STAGE(st, (kt + NSTAGE - 1) << 4);
        } else {
            asm volatile("cp.async.commit_group;");
        }
        const float* Ab = sm + cur * ASZ;
        const float* Bb = sm + NSTAGE * ASZ + cur * BSZ;
#pragma unroll
        for (int ks = 0; ks < 2; ks++) {
            const int kf = ks * 8 + tc4;
            uint32_t af[4][4];
#pragma unroll
            for (int mt = 0; mt < 4; mt++) {
                int m0 = wm * 64 + mt * 16 + g;
                af[mt][0] = __float_as_uint(Ab[m0 * 20 + kf]);
                af[mt][1] = __float_as_uint(Ab[(m0 + 8) * 20 + kf]);
                af[mt][2] = __float_as_uint(Ab[m0 * 20 + kf + 4]);
                af[mt][3] = __float_as_uint(Ab[(m0 + 8) * 20 + kf + 4]);
            }
            const float* Bk0 = Bb + kf * 136;
            const float* Bk1 = Bb + (kf + 4) * 136;
            uint32_t bf[4][2];
#pragma unroll
            for (int nt = 0; nt < 4; nt++) {
                int n0 = wn * 32 + nt * 8 + g;
                bf[nt][0] = __float_as_uint(Bk0[n0]);
                bf[nt][1] = __float_as_uint(Bk1[n0]);
            }
#pragma unroll
            for (int mt = 0; mt < 4; mt++)
#pragma unroll
                for (int nt = 0; nt < 4; nt++) {
                    asm volatile(
                        "mma.sync.aligned.m16n8k8.row.col.f32.tf32.tf32.f32 "
                        "{%0,%1,%2,%3}, {%4,%5,%6,%7}, {%8,%9}, {%0,%1,%2,%3};"
                        : "+f"(acc[mt][nt][0]), "+f"(acc[mt][nt][1]),
                          "+f"(acc[mt][nt][2]), "+f"(acc[mt][nt][3])
                        : "r"(af[mt][0]), "r"(af[mt][1]), "r"(af[mt][2]), "r"(af[mt][3]),
                          "r"(bf[nt][0]), "r"(bf[nt][1]));
                }
        }
        cur = (cur + 1) % NSTAGE;
    }
#undef ISSUE_STAGE

#pragma unroll
    for (int mt = 0; mt < 4; mt++) {
        int r0 = rowBase + wm * 64 + mt * 16 + g;
#pragma unroll
        for (int nt = 0; nt < 4; nt++) {
            int cc = colBase + wn * 32 + nt * 8 + tc4 * 2;
            float c0 = acc[mt][nt][0], c1 = acc[mt][nt][1];
            float c2 = acc[mt][nt][2], c3 = acc[mt][nt][3];
            if (roundOut) {
                c0 = to_tf32(c0); c1 = to_tf32(c1); c2 = to_tf32(c2); c3 = to_tf32(c3);
            }
            if (cc + 1 < Nn) {
                *(float2*)(C + (size_t)r0 * Nn + cc) = make_float2(c0, c1);
                *(float2*)(C + (size_t)(r0 + 8) * Nn + cc) = make_float2(c2, c3);
            } else if (cc < Nn) {
                C[(size_t)r0 * Nn + cc] = c0;
                C[(size_t)(r0 + 8) * Nn + cc] = c2;
            }
        }
    }
}

// ---------------- dedicated gate GEMM: N=12, warp-per-row ----------------
__global__ void __launch_bounds__(256) gate_kernel(const float* __restrict__ x,
                                                   const float* __restrict__ gW) {
    int row = blockIdx.x * 8 + (threadIdx.x >> 5);
    int lane = threadIdx.x & 31;
    const float* xr = x + (size_t)row * DD;
    float acc[KK];
#pragma unroll
    for (int j = 0; j < KK; j++) acc[j] = 0.0f;
    for (int k = lane; k < DD; k += 32) {
        float xv = xr[k];
        const float* gp = gW + (size_t)k * KK;
#pragma unroll
        for (int j = 0; j < KK; j++) acc[j] += xv * gp[j];
    }
#pragma unroll
    for (int j = 0; j < KK; j++) {
        float v = acc[j];
#pragma unroll
        for (int d = 16; d > 0; d >>= 1) v += __shfl_down_sync(0xffffffffu, v, d);
        if (lane == 0) g_gatelin[(size_t)row * KK + j] = v;
    }
}

// ---------------- depthwise causal conv + transpose to (b,k,h,t) ----------
__global__ void conv_kernel(const float* __restrict__ ck, const float* __restrict__ sscale) {
    __shared__ float tile[32][33];
    int b = blockIdx.z;
    int cBase = blockIdx.x * 32;
    int tBase = blockIdx.y * 32;
    int c = cBase + threadIdx.x;
    float kc[4] = {0.f, 0.f, 0.f, 0.f};
    if (c < ZC) {
#pragma unroll
        for (int j = 0; j < 4; j++) kc[j] = ck[j * ZC + c];
    }
#pragma unroll
    for (int i = 0; i < 4; i++) {
        int t = tBase + threadIdx.y + i * 8;
        float val = 0.0f;
        if (c < ZC) {
#pragma unroll
            for (int j = 0; j < 4; j++) {
                int tt = t - 3 + j;
                if (tt >= 0) val += g_z0[((size_t)(b * LL + tt)) * ZC + c] * kc[j];
            }
        }
        tile[threadIdx.x][threadIdx.y + i * 8] = val;
    }
    __syncthreads();
    int tid = threadIdx.y * 32 + threadIdx.x;
#pragma unroll
    for (int i = 0; i < 4; i++) {
        int idx = tid + i * 256;
        int cl = idx >> 5, tl = idx & 31;
        int cc = cBase + cl;
        int t = tBase + tl;
        if (cc < MEMn) {
            int k = cc >> 6, h = cc & 63;
            g_kval[(((size_t)b * KK + k) * HH + h) * LL + t] = tile[cl][tl];
        } else if (cc < ZC) {
            int k = cc - MEMn;
            float v = tile[cl][tl];
            float lp = fminf(fmaxf(sscale[k] * v, -20.0f), 20.0f);
            float ltw = -g_slope[k] * (float)(LL - 1 - t);
            g_pw[((size_t)b * KK + k) * LL + t] = __expf(lp + ltw);
        }
    }
}

// ---------------- per-chunk partial sums (warp-autonomous, chunk=32) ------
__global__ void __launch_bounds__(256) chunksum_kernel(const float* __restrict__ tscale) {
    int bk = blockIdx.z;
    int k = bk % KK;
    int h = blockIdx.y;
    int w = threadIdx.x >> 5, lane = threadIdx.x & 31;
    int chunk = blockIdx.x * 8 + w;
    int t = chunk * LC2 + lane;

    float pw = g_pw[(size_t)bk * LL + t];
    float kv = g_kval[(((size_t)bk) * HH + h) * LL + t];
    float kvw = kv * pw;
    float tanhv = tanhf(tscale[k] * kv);
    int thb = (k * HH + h) * MM;
    float vals[9];
#pragma unroll
    for (int m = 0; m < MM; m++) {
        float s, c2;
        __sincosf(tanhv * g_theta[thb + m], &s, &c2);
        vals[2 * m] = kvw * c2;
        vals[2 * m + 1] = kvw * s;
    }
    vals[8] = pw;

#pragma unroll
    for (int j = 0; j < 9; j++) {
        float x = vals[j];
#pragma unroll
        for (int d = 16; d > 0; d >>= 1) x += __shfl_xor_sync(0xffffffffu, x, d);
        vals[j] = x;
    }
    if (lane == 0) {
#pragma unroll
        for (int j = 0; j < 8; j++) {
            int m = j >> 1, ri = j & 1;
            size_t ch = (((size_t)bk * HH + h) * MM + m) * 2 + ri;
            g_csum[ch * NCH2 + chunk] = vals[j];
        }
        if (h == 0) g_dsum[(size_t)bk * NCH2 + chunk] = vals[8];
    }
}

// ---------------- exclusive scan of chunk sums (phase 2) ----------------
__global__ void scanoff_kernel() {
    int idx = blockIdx.x * 256 + threadIdx.x;
    const int NRI = BB * KK * HH * MM * 2;
    if (idx < NRI) {
        float run = 0.0f;
#pragma unroll 8
        for (int c = 0; c < NCH2; c++) {
            float x = g_csum[(size_t)idx * NCH2 + c];
            g_coff[(size_t)idx * NCH2 + c] = run;
            run += x;
        }
    } else if (idx < NRI + BB * KK) {
        int d = idx - NRI;
        float run = 0.0f;
#pragma unroll 8
        for (int c = 0; c < NCH2; c++) {
            float x = g_dsum[(size_t)d * NCH2 + c];
            g_doff[(size_t)d * NCH2 + c] = run;
            run += x;
        }
    }
}

// ---------------- fused in-chunk scan + q-combine (h-split, coalesced) ----
__global__ void __launch_bounds__(256) phase3_kernel(const float* __restrict__ tscale,
                                                     const float* __restrict__ nscale) {
    __shared__ float tile[8][32][33];
    int bz = blockIdx.z;            // b * 4 + hq
    int b = bz >> 2, hq = bz & 3;
    int k = blockIdx.y;
    int w = threadIdx.x >> 5, lane = threadIdx.x & 31;
    int chunk = blockIdx.x * 8 + w;
    int t = chunk * LC2 + lane;
    int bk = b * KK + k;

    float pw = g_pw[(size_t)bk * LL + t];
    float x = pw;
#pragma unroll
    for (int d = 1; d < 32; d <<= 1) {
        float n = __shfl_up_sync(0xffffffffu, x, d);
        if (lane >= d) x += n;
    }
    float den = g_doff[(size_t)bk * NCH2 + chunk] + x;
    float invden = 1.0f / fmaxf(den, 1e-4f);

    int kq = k >> 1;
    const float* qbase = g_qt + ((size_t)(b * 3072 + kq * 512)) * LL + t;
    float ts = tscale[k];
    size_t kvbase = ((size_t)bk * HH) * LL + t;
    size_t chb_base = ((size_t)bk * HH) * MM;
    int thb_base = (k * HH) * MM;

    const int h0 = hq * 16;
    for (int hl = 0; hl < 16; hl++) {
        int h = h0 + hl;
        float kv = g_kval[kvbase + (size_t)h * LL];
        float kvw = kv * pw;
        float tanhv = tanhf(ts * kv);
        const float* qp = qbase + (size_t)(h * 8) * LL;
        float qv[8];
#pragma unroll
        for (int j = 0; j < 8; j++) qv[j] = qp[(size_t)j * LL];
        int thb = thb_base + h * MM;
        size_t chb = chb_base + (size_t)h * MM;
        float v[8];
#pragma unroll
        for (int m = 0; m < MM; m++) {
            float s, c2;
            __sincosf(tanhv * g_theta[thb + m], &s, &c2);
            v[2 * m] = kvw * c2;
            v[2 * m + 1] = kvw * s;
        }
#pragma unroll
        for (int j = 0; j < 8; j++) {
            float y = v[j];
#pragma unroll
            for (int d = 1; d < 32; d <<= 1) {
                float n = __shfl_up_sync(0xffffffffu, y, d);
                if (lane >= d) y += n;
            }
            v[j] = y;
        }
        float accre = 0.0f, accim = 0.0f;
#pragma unroll
        for (int m = 0; m < MM; m++) {
            float offre = g_coff[((chb + m) * 2 + 0) * NCH2 + chunk];
            float offim = g_coff[((chb + m) * 2 + 1) * NCH2 + chunk];
            float sre = (offre + v[2 * m]) * invden;
            float sim = (offim + v[2 * m + 1]) * invden;
            float wg = g_wint[thb + m];
            float qr = qv[2 * m], qi = qv[2 * m + 1];
            accre += (sre * qr + sim * qi) * wg;
            accim += (sim * qr - sre * qi) * wg;
        }
        float ns = nscale[k * HH + h];
        tile[w][lane][hl] = to_tf32(accre * ns);
        tile[w][lane][16 + hl] = to_tf32(accim * ns);
    }
    __syncwarp();
    size_t Abase = ((size_t)k * BL + (size_t)b * LL + (size_t)chunk * LC2) * 128;
    int hh = (lane < 16) ? (h0 + lane) : (64 + h0 + (lane - 16));
    for (int r = 0; r < 32; r++) {
        g_A[Abase + (size_t)r * 128 + hh] = tile[w][r][lane];
    }
}

// ---------------- gate/highway/silu epilogue (rounds: feeds final GEMM) ---
__global__ void combine2_kernel(const float* __restrict__ gate_b,
                                const float* __restrict__ hscale) {
    int idx = blockIdx.x * 256 + threadIdx.x;
    if (idx >= BL * 2304) return;
    int row = idx / 2304, n = idx % 2304;
    int k = n / EXPn, e = n % EXPn;
    size_t sb = ((size_t)k * BL + row) * DSWn;
    float sv = g_yspec[sb + e];
    float sg = g_yspec[sb + EXPn + e];
    size_t db = (size_t)row * 4608 + (size_t)k * DSWn;
    float dv = g_ydir[db + e];
    float dg = g_ydir[db + EXPn + e];
    float gate = 1.0f / (1.0f + __expf(-(g_gatelin[(size_t)row * KK + k] + gate_b[k])));
    float hs = hscale[k];
    float val = sv * gate + dv * hs;
    float gt = sg * gate + dg * hs;
    g_yfin[(size_t)row * 2304 + n] = to_tf32(val * gt / (1.0f + __expf(-gt)));
}

// ---------------- host launcher (multi-stream fork/join, capturable) ------
extern "C" void kernel_launch(void* const* d_in, const int* in_sizes, int n_in,
                              void* d_out, int out_size) {
    const float* x = (const float*)d_in[0];
    const float* W_mem = (const float*)d_in[1];
    const float* conv_k = (const float*)d_in[2];
    const float* W_q = (const float*)d_in[3];
    const float* theta_raw = (const float*)d_in[4];
    const float* decay = (const float*)d_in[5];
    const float* sscale = (const float*)d_in[6];
    const float* tscale = (const float*)d_in[7];
    const float* W_re = (const float*)d_in[8];
    const float* W_im = (const float*)d_in[9];
    const float* nscale = (const float*)d_in[10];
    const float* gate_W = (const float*)d_in[11];
    const float* gate_b = (const float*)d_in[12];
    const float* skip_down = (const float*)d_in[13];
    const float* skip_up = (const float*)d_in[14];
    const float* hscale = (const float*)d_in[15];
    const float* out_W = (const float*)d_in[16];

    float *z0, *q, *lat, *ydir, *A, *wcat, *yspec, *yfin;
    float *xr, *wmemr, *wqr, *sdr, *sur, *owr;
    cudaGetSymbolAddress((void**)&z0, g_z0);
    cudaGetSymbolAddress((void**)&q, g_q);
    cudaGetSymbolAddress((void**)&lat, g_lat);
    cudaGetSymbolAddress((void**)&ydir, g_ydir);
    cudaGetSymbolAddress((void**)&A, g_A);
    cudaGetSymbolAddress((void**)&wcat, g_wcat);
    cudaGetSymbolAddress((void**)&yspec, g_yspec);
    cudaGetSymbolAddress((void**)&yfin, g_yfin);
    cudaGetSymbolAddress((void**)&xr, g_xr);
    cudaGetSymbolAddress((void**)&wmemr, g_wmemr);
    cudaGetSymbolAddress((void**)&wqr, g_wqr);
    cudaGetSymbolAddress((void**)&sdr, g_sdr);
    cudaGetSymbolAddress((void**)&sur, g_sur);
    cudaGetSymbolAddress((void**)&owr, g_owr);

    static cudaStream_t s1 = 0, s2 = 0, s3 = 0;
    static cudaEvent_t eR1 = 0, eR2 = 0, eQT0 = 0, eQT1 = 0, eDir = 0;
    static cudaEvent_t eP = 0, eY1 = 0, eC = 0, eTail = 0;
    static int init_done = 0;
    if (!init_done) {
        cudaFuncSetAttribute(tgemm_kernel, cudaFuncAttributeMaxDynamicSharedMemorySize,
                             SMEM_BYTES);
        cudaStreamCreateWithFlags(&s1, cudaStreamNonBlocking);
        cudaStreamCreateWithFlags(&s2, cudaStreamNonBlocking);
        cudaStreamCreateWithFlags(&s3, cudaStreamNonBlocking);
        cudaEventCreateWithFlags(&eR1, cudaEventDisableTiming);
        cudaEventCreateWithFlags(&eR2, cudaEventDisableTiming);
        cudaEventCreateWithFlags(&eQT0, cudaEventDisableTiming);
        cudaEventCreateWithFlags(&eQT1, cudaEventDisableTiming);
        cudaEventCreateWithFlags(&eDir, cudaEventDisableTiming);
        cudaEventCreateWithFlags(&eP, cudaEventDisableTiming);
        cudaEventCreateWithFlags(&eY1, cudaEventDisableTiming);
        cudaEventCreateWithFlags(&eC, cudaEventDisableTiming);
        cudaEventCreateWithFlags(&eTail, cudaEventDisableTiming);
        init_done = 1;
    }

    // ---- prologue: x/W_q round first so q halves can start ASAP ----
    round_p1_kernel<<<(RT1 + 255) / 256, 256>>>(x, W_q);
    cudaEventRecord(eR1, 0);
    cudaStreamWaitEvent(s1, eR1, 0);
    cudaStreamWaitEvent(s3, eR1, 0);

    // ---- s1/s3: q GEMM column halves; each followed by its qt half -------
    tgemm_kernel<<<dim3(12, 32, 1), 256, SMEM_BYTES, s1>>>(xr, wqr, q, 3072, DD, 0, 0, 0, 0);
    qt_kernel<<<dim3(48, 128), dim3(32, 8), 0, s1>>>(0);
    cudaEventRecord(eQT0, s1);
    tgemm_kernel<<<dim3(12, 32, 1), 256, SMEM_BYTES, s3>>>(xr, wqr + 1536, q + 1536,
                                                           3072, DD, 0, 0, 0, 0);
    qt_kernel<<<dim3(48, 128), dim3(32, 8), 0, s3>>>(1536);
    cudaEventRecord(eQT1, s3);

    // ---- rest of prologue on main stream ----
    round_p2_kernel<<<(RT2 + 255) / 256, 256>>>(W_mem, skip_down, skip_up, out_W);
    precompute_kernel<<<3, 256>>>(theta_raw, decay);
    wcat_kernel<<<(KK * 128 * DSWn + 255) / 256, 256>>>(W_re, W_im);
    cudaEventRecord(eR2, 0);
    cudaStreamWaitEvent(s2, eR2, 0);

    // ---- side stream s2: skip path + gate ----
    tgemm_kernel<<<dim3(2, 32, 1), 256, SMEM_BYTES, s2>>>(xr, sdr, lat, LATn, DD, 0, 0, 0, 1);
    tgemm_kernel<<<dim3(36, 32, 1), 256, SMEM_BYTES, s2>>>(lat, sur, ydir, 4608, LATn, 0, 0, 0, 0);
    gate_kernel<<<BL / 8, 256, 0, s2>>>(x, gate_W);
    cudaEventRecord(eDir, s2);

    // ---- main critical chain ----
    tgemm_kernel<<<dim3(7, 32, 1), 256, SMEM_BYTES>>>(xr, wmemr, z0, ZC, DD, 0, 0, 0, 0);
    conv_kernel<<<dim3(25, 64, BB), dim3(32, 8)>>>(conv_k, sscale);
    chunksum_kernel<<<dim3(8, HH, BB * KK), 256>>>(tscale);
    scanoff_kernel<<<(BB * KK * HH * MM * 2 + BB * KK + 255) / 256, 256>>>();
    cudaStreamWaitEvent(0, eQT0, 0);
    cudaStreamWaitEvent(0, eQT1, 0);
    phase3_kernel<<<dim3(8, KK, BB * 4), 256>>>(tscale, nscale);
    cudaEventRecord(eP, 0);

    // ---- yspec split by k across s1 (k=0..5) and main (k=6..11) ----
    cudaStreamWaitEvent(s1, eP, 0);
    tgemm_kernel<<<dim3(3, 32, 6), 256, SMEM_BYTES, s1>>>(
        A, wcat, yspec, DSWn, 128,
        (size_t)BL * 128, (size_t)128 * DSWn, (size_t)BL * DSWn, 0);
    cudaEventRecord(eY1, s1);
    tgemm_kernel<<<dim3(3, 32, 6), 256, SMEM_BYTES>>>(
        A + (size_t)6 * BL * 128, wcat + (size_t)6 * 128 * DSWn,
        yspec + (size_t)6 * BL * DSWn, DSWn, 128,
        (size_t)BL * 128, (size_t)128 * DSWn, (size_t)BL * DSWn, 0);

    // ---- combine2 (needs both yspec halves + skip path) ----
    cudaStreamWaitEvent(0, eY1, 0);
    cudaStreamWaitEvent(0, eDir, 0);
    combine2_kernel<<<((size_t)BL * 2304 + 255) / 256, 256>>>(gate_b, hscale);
    cudaEventRecord(eC, 0);

    // ---- out GEMM split by row halves across s1 and main ----
    cudaStreamWaitEvent(s1, eC, 0);
    tgemm_kernel<<<dim3(6, 16, 1), 256, SMEM_BYTES, s1>>>(
        yfin, owr, (float*)d_out, DD, 2304, 0, 0, 0, 0);
    cudaEventRecord(eTail, s1);
    tgemm_kernel<<<dim3(6, 16, 1), 256, SMEM_BYTES>>>(
        yfin + (size_t)2048 * 2304, owr, (float*)d_out + (size_t)2048 * DD,
        DD, 2304, 0, 0, 0, 0);
    cudaStreamWaitEvent(0, eTail, 0);
}

// round 16
// speedup vs baseline: 1.3552x; 1.3102x over previous
#include <cuda_runtime.h>
#include <cuda_fp16.h>
#include <math.h>
#include <stdint.h>

// ---------------- problem constants ----------------
#define BB 2
#define LL 2048
#define DD 768
#define KK 12
#define KQn 6
#define MM 4
#define HH 64
#define MEMn 768
#define EXPn 192
#define DSWn 384
#define LATn 192
#define BL 4096            // B*L
#define ZC 780             // MEM + K
#define NCH2 64            // scan chunks
#define LC2 32             // chunk length (warp-sized)

// fp16 GEMM smem staging geometry
#define HPITCH 24                  // halves per row (48B, 16B-aligned, conflict-free)
#define HASZ (128 * HPITCH)        // halves per operand stage (3072)
#define NSTAGE 5
#define SMEM_BYTES (NSTAGE * 2 * HASZ * 2)   // 61440 bytes

// ---------------- scratch (device globals, no allocs) ----------------
__device__ float g_z0[(size_t)BL * ZC];
__device__ float g_q[(size_t)BL * 3072];
__device__ float g_qt[(size_t)BL * 3072];
__device__ float g_gatelin[(size_t)BL * KK];
__device__ float g_lat[(size_t)BL * LATn];
__device__ float g_ydir[(size_t)BL * 4608];
__device__ float g_kval[(size_t)BB * KK * HH * LL];
__device__ float g_pw[(size_t)BB * KK * LL];
__device__ float g_theta[KK * HH * MM];
__device__ float g_wint[KK * HH * MM];
__device__ float g_slope[KK];
__device__ float g_csum[(size_t)BB * KK * HH * MM * 2 * NCH2];
__device__ float g_coff[(size_t)BB * KK * HH * MM * 2 * NCH2];
__device__ float g_dsum[(size_t)BB * KK * NCH2];
__device__ float g_doff[(size_t)BB * KK * NCH2];
__device__ float g_yspec[(size_t)KK * BL * DSWn];
// fp16 GEMM operands
__device__ __half g_xrh[(size_t)BL * DD];
__device__ __half g_wqt[(size_t)3072 * DD];       // Wq^T [col][kk]
__device__ __half g_wmemt[(size_t)896 * DD];      // Wmem^T [n][kk], 780 rows valid
__device__ __half g_sdt[(size_t)LATn * DD];       // skip_down^T
__device__ __half g_sut[(size_t)4608 * LATn];     // skip_up^T
__device__ __half g_owt[(size_t)DD * 2304];       // out_W^T
__device__ __half g_wcatt[(size_t)KK * DSWn * 128]; // per-k [n][kk]
__device__ __half g_Ah[(size_t)KK * BL * 128];
__device__ __half g_lath[(size_t)BL * LATn];
__device__ __half g_yfinh[(size_t)BL * 2304];

__device__ __forceinline__ float softplusf(float x) {
    return (x > 20.0f) ? x : log1pf(__expf(x));
}

__device__ __forceinline__ void cp_async16(uint32_t saddr, const void* gptr, int src_bytes) {
    asm volatile("cp.async.cg.shared.global [%0], [%1], 16, %2;"
                 :: "r"(saddr), "l"(gptr), "r"(src_bytes));
}

// ---------------- x -> half (flat) ----------------
__global__ void hx_kernel(const float* __restrict__ x) {
    int i = blockIdx.x * 256 + threadIdx.x;
    if (i >= BL * DD / 4) return;
    float4 v = ((const float4*)x)[i];
    ((__half2*)g_xrh)[i * 2] = __floats2half2_rn(v.x, v.y);
    ((__half2*)g_xrh)[i * 2 + 1] = __floats2half2_rn(v.z, v.w);
}

// ---------------- lat -> half (flat) ----------------
__global__ void lath_kernel() {
    int i = blockIdx.x * 256 + threadIdx.x;
    if (i >= BL * LATn / 4) return;
    float4 v = ((const float4*)g_lat)[i];
    ((__half2*)g_lath)[i * 2] = __floats2half2_rn(v.x, v.y);
    ((__half2*)g_lath)[i * 2 + 1] = __floats2half2_rn(v.z, v.w);
}

// ---------------- transpose+half: src[K][N] -> dst[N][K] ------------------
__global__ void htrans_kernel(const float* __restrict__ src, __half* __restrict__ dst,
                              int Kdim, int Ndim) {
    __shared__ float tile[32][33];
    int nb = blockIdx.x * 32, kb = blockIdx.y * 32;
#pragma unroll
    for (int i = 0; i < 4; i++) {
        int k = kb + threadIdx.y + i * 8;
        int n = nb + threadIdx.x;
        tile[threadIdx.y + i * 8][threadIdx.x] = (n < Ndim) ? src[(size_t)k * Ndim + n] : 0.0f;
    }
    __syncthreads();
#pragma unroll
    for (int i = 0; i < 4; i++) {
        int n = nb + threadIdx.y + i * 8;
        if (n < Ndim)
            dst[(size_t)n * Kdim + kb + threadIdx.x] =
                __float2half(tile[threadIdx.x][threadIdx.y + i * 8]);
    }
}

// ---------------- wcat transposed+half: [k][n][kk] ------------------------
__global__ void wcatt_kernel(const float* __restrict__ Wre, const float* __restrict__ Wim) {
    __shared__ float tile[32][33];
    int k = blockIdx.z;
    int nb = blockIdx.x * 32;
    int rb = blockIdx.y * 32;
#pragma unroll
    for (int i = 0; i < 4; i++) {
        int r = rb + threadIdx.y + i * 8;
        int n = nb + threadIdx.x;
        float v = (r < HH) ? Wre[((size_t)k * HH + r) * DSWn + n]
                           : Wim[((size_t)k * HH + (r - HH)) * DSWn + n];
        tile[threadIdx.y + i * 8][threadIdx.x] = v;
    }
    __syncthreads();
#pragma unroll
    for (int i = 0; i < 4; i++) {
        int n = nb + threadIdx.y + i * 8;
        g_wcatt[((size_t)k * DSWn + n) * 128 + rb + threadIdx.x] =
            __float2half(tile[threadIdx.x][threadIdx.y + i * 8]);
    }
}

// ---------------- q transpose: [BL][3072] -> [(b*3072+col)*LL + t] --------
__global__ void qt_kernel() {
    __shared__ float tile[32][33];
    int cb = blockIdx.x * 32;
    int rb = blockIdx.y * 32;
#pragma unroll
    for (int i = 0; i < 4; i++) {
        int r = rb + threadIdx.y + i * 8;
        tile[threadIdx.y + i * 8][threadIdx.x] = g_q[(size_t)r * 3072 + cb + threadIdx.x];
    }
    __syncthreads();
    int b = rb >> 11;
    int tloc = (rb & 2047) + threadIdx.x;
#pragma unroll
    for (int i = 0; i < 4; i++) {
        int col = cb + threadIdx.y + i * 8;
        g_qt[((size_t)(b * 3072 + col)) * LL + tloc] = tile[threadIdx.x][threadIdx.y + i * 8];
    }
}

// ---------------- precompute theta / w_int / slopes ----------------
__global__ void precompute_kernel(const float* __restrict__ theta_raw,
                                  const float* __restrict__ decay) {
    int tid = blockIdx.x * blockDim.x + threadIdx.x;
    if (tid < KK * HH) {
        float ta[MM];
        float run = 0.0f;
#pragma unroll
        for (int m = 0; m < MM; m++) {
            run += softplusf(theta_raw[tid * MM + m]) + 1e-4f;
            ta[m] = run;
        }
        float total = ta[MM - 1];
        float sc = 2.999f / total;
        float dth[MM - 1];
#pragma unroll
        for (int i = 0; i < MM - 1; i++) dth[i] = (ta[i + 1] - ta[i]) * sc;
#pragma unroll
        for (int m = 0; m < MM; m++) g_theta[tid * MM + m] = 0.001f + ta[m] * sc;
        g_wint[tid * MM + 0] = dth[0] * 0.5f;
        g_wint[tid * MM + 1] = 0.5f * (dth[0] + dth[1]);
        g_wint[tid * MM + 2] = 0.5f * (dth[1] + dth[2]);
        g_wint[tid * MM + 3] = dth[2] * 0.5f;
    }
    if (tid < KK) g_slope[tid] = softplusf(decay[tid]);
}

// ---------------- fp16 tensor GEMM: C = A[M,K] @ Bt[N,K]^T ----------------
// A row-major half, Bt row-major half ([n][k]). C float, stride ldC, bound Nn.
// M mult of 128, K mult of 16.
__global__ void __launch_bounds__(256, 2) hgemm_kernel(
    const __half* __restrict__ A, const __half* __restrict__ Bt, float* __restrict__ C,
    int Nn, int ldC, int Kk, size_t sA, size_t sB, size_t sC) {
    A += (size_t)blockIdx.z * sA;
    Bt += (size_t)blockIdx.z * sB;
    C += (size_t)blockIdx.z * sC;

    extern __shared__ __half smh[];
    const uint32_t smu = (uint32_t)__cvta_generic_to_shared(smh);

    const int tid = threadIdx.x;
    const int lane = tid & 31;
    const int wid = tid >> 5;
    const int wm = wid >> 2;            // 0..1 (64 rows)
    const int wn = wid & 3;             // 0..3 (32 cols)
    const int g = lane >> 2;            // 0..7
    const int tc4 = lane & 3;           // 0..3

    const int rowBase = blockIdx.y * 128;
    const int colBase = blockIdx.x * 128;

    // staging: one A chunk + one B chunk per thread (16B = 8 halves)
    const int sRow = tid >> 1;
    const int sKc = (tid & 1) * 8;

    float acc[4][4][4];
#pragma unroll
    for (int i = 0; i < 4; i++)
#pragma unroll
        for (int j = 0; j < 4; j++)
#pragma unroll
            for (int r = 0; r < 4; r++) acc[i][j][r] = 0.0f;

    const int KT = Kk >> 4;

#define ISSUE_STAGE(st, k0)                                                     \
    {                                                                           \
        uint32_t ab = smu + (uint32_t)(st) * (HASZ * 2);                        \
        uint32_t bb = smu + (uint32_t)(NSTAGE + (st)) * (HASZ * 2);             \
        cp_async16(ab + (uint32_t)(sRow * 48 + sKc * 2),                        \
                   A + (size_t)(rowBase + sRow) * Kk + (k0) + sKc, 16);         \
        int bOk = (colBase + sRow < Nn) ? 16 : 0;                               \
        const __half* bp = (colBase + sRow < Nn)                                \
            ? Bt + (size_t)(colBase + sRow) * Kk + (k0) + sKc : Bt;             \
        cp_async16(bb + (uint32_t)(sRow * 48 + sKc * 2), bp, bOk);              \
        asm volatile("cp.async.commit_group;");                                 \
    }

#pragma unroll
    for (int s = 0; s < NSTAGE - 1; s++) {
        if (s < KT) { ISSUE_STAGE(s, s << 4); }
        else { asm volatile("cp.async.commit_group;"); }
    }

    int cur = 0;
    for (int kt = 0; kt < KT; kt++) {
        asm volatile("cp.async.wait_group %0;" :: "n"(NSTAGE - 2));
        __syncthreads();
        if (kt + NSTAGE - 1 < KT) {
            int st = (kt + NSTAGE - 1) % NSTAGE;
            ISSUE_STAGE(st, (kt + NSTAGE - 1) << 4);
        } else {
            asm volatile("cp.async.commit_group;");
        }
        const __half* Ab = smh + (size_t)cur * HASZ;
        const __half* Bb = smh + (size_t)(NSTAGE + cur) * HASZ;
        uint32_t af[4][4];
#pragma unroll
        for (int mt = 0; mt < 4; mt++) {
            int r0 = wm * 64 + mt * 16 + g;
            af[mt][0] = *(const uint32_t*)&Ab[r0 * HPITCH + 2 * tc4];
            af[mt][1] = *(const uint32_t*)&Ab[(r0 + 8) * HPITCH + 2 * tc4];
            af[mt][2] = *(const uint32_t*)&Ab[r0 * HPITCH + 2 * tc4 + 8];
            af[mt][3] = *(const uint32_t*)&Ab[(r0 + 8) * HPITCH + 2 * tc4 + 8];
        }
        uint32_t bf[4][2];
#pragma unroll
        for (int nt = 0; nt < 4; nt++) {
            int n0 = wn * 32 + nt * 8 + g;
            bf[nt][0] = *(const uint32_t*)&Bb[n0 * HPITCH + 2 * tc4];
            bf[nt][1] = *(const uint32_t*)&Bb[n0 * HPITCH + 2 * tc4 + 8];
        }
#pragma unroll
        for (int mt = 0; mt < 4; mt++)
#pragma unroll
            for (int nt = 0; nt < 4; nt++) {
                asm volatile(
                    "mma.sync.aligned.m16n8k16.row.col.f32.f16.f16.f32 "
                    "{%0,%1,%2,%3}, {%4,%5,%6,%7}, {%8,%9}, {%0,%1,%2,%3};"
                    : "+f"(acc[mt][nt][0]), "+f"(acc[mt][nt][1]),
                      "+f"(acc[mt][nt][2]), "+f"(acc[mt][nt][3])
                    : "r"(af[mt][0]), "r"(af[mt][1]), "r"(af[mt][2]), "r"(af[mt][3]),
                      "r"(bf[nt][0]), "r"(bf[nt][1]));
            }
        cur = (cur + 1) % NSTAGE;
    }
#undef ISSUE_STAGE

    // ---- epilogue ----
#pragma unroll
    for (int mt = 0; mt < 4; mt++) {
        int r0 = rowBase + wm * 64 + mt * 16 + g;
#pragma unroll
        for (int nt = 0; nt < 4; nt++) {
            int cc = colBase + wn * 32 + nt * 8 + tc4 * 2;
            if (cc + 1 < Nn) {
                *(float2*)(C + (size_t)r0 * ldC + cc) = make_float2(acc[mt][nt][0], acc[mt][nt][1]);
                *(float2*)(C + (size_t)(r0 + 8) * ldC + cc) = make_float2(acc[mt][nt][2], acc[mt][nt][3]);
            } else if (cc < Nn) {
                C[(size_t)r0 * ldC + cc] = acc[mt][nt][0];
                C[(size_t)(r0 + 8) * ldC + cc] = acc[mt][nt][2];
            }
        }
    }
}

// ---------------- dedicated gate GEMM: N=12, warp-per-row ----------------
__global__ void __launch_bounds__(256) gate_kernel(const float* __restrict__ x,
                                                   const float* __restrict__ gW) {
    int row = blockIdx.x * 8 + (threadIdx.x >> 5);
    int lane = threadIdx.x & 31;
    const float* xr = x + (size_t)row * DD;
    float acc[KK];
#pragma unroll
    for (int j = 0; j < KK; j++) acc[j] = 0.0f;
    for (int k = lane; k < DD; k += 32) {
        float xv = xr[k];
        const float* gp = gW + (size_t)k * KK;
#pragma unroll
        for (int j = 0; j < KK; j++) acc[j] += xv * gp[j];
    }
#pragma unroll
    for (int j = 0; j < KK; j++) {
        float v = acc[j];
#pragma unroll
        for (int d = 16; d > 0; d >>= 1) v += __shfl_down_sync(0xffffffffu, v, d);
        if (lane == 0) g_gatelin[(size_t)row * KK + j] = v;
    }
}

// ---------------- depthwise causal conv + transpose to (b,k,h,t) ----------
__global__ void conv_kernel(const float* __restrict__ ck, const float* __restrict__ sscale) {
    __shared__ float tile[32][33];
    int b = blockIdx.z;
    int cBase = blockIdx.x * 32;
    int tBase = blockIdx.y * 32;
    int c = cBase + threadIdx.x;
    float kc[4] = {0.f, 0.f, 0.f, 0.f};
    if (c < ZC) {
#pragma unroll
        for (int j = 0; j < 4; j++) kc[j] = ck[j * ZC + c];
    }
#pragma unroll
    for (int i = 0; i < 4; i++) {
        int t = tBase + threadIdx.y + i * 8;
        float val = 0.0f;
        if (c < ZC) {
#pragma unroll
            for (int j = 0; j < 4; j++) {
                int tt = t - 3 + j;
                if (tt >= 0) val += g_z0[((size_t)(b * LL + tt)) * ZC + c] * kc[j];
            }
        }
        tile[threadIdx.x][threadIdx.y + i * 8] = val;
    }
    __syncthreads();
    int tid = threadIdx.y * 32 + threadIdx.x;
#pragma unroll
    for (int i = 0; i < 4; i++) {
        int idx = tid + i * 256;
        int cl = idx >> 5, tl = idx & 31;
        int cc = cBase + cl;
        int t = tBase + tl;
        if (cc < MEMn) {
            int k = cc >> 6, h = cc & 63;
            g_kval[(((size_t)b * KK + k) * HH + h) * LL + t] = tile[cl][tl];
        } else if (cc < ZC) {
            int k = cc - MEMn;
            float v = tile[cl][tl];
            float lp = fminf(fmaxf(sscale[k] * v, -20.0f), 20.0f);
            float ltw = -g_slope[k] * (float)(LL - 1 - t);
            g_pw[((size_t)b * KK + k) * LL + t] = __expf(lp + ltw);
        }
    }
}

// ---------------- per-chunk partial sums (warp-autonomous, chunk=32) ------
__global__ void __launch_bounds__(256) chunksum_kernel(const float* __restrict__ tscale) {
    int bk = blockIdx.z;
    int k = bk % KK;
    int h = blockIdx.y;
    int w = threadIdx.x >> 5, lane = threadIdx.x & 31;
    int chunk = blockIdx.x * 8 + w;
    int t = chunk * LC2 + lane;

    float pw = g_pw[(size_t)bk * LL + t];
    float kv = g_kval[(((size_t)bk) * HH + h) * LL + t];
    float kvw = kv * pw;
    float tanhv = tanhf(tscale[k] * kv);
    int thb = (k * HH + h) * MM;
    float vals[9];
#pragma unroll
    for (int m = 0; m < MM; m++) {
        float s, c2;
        __sincosf(tanhv * g_theta[thb + m], &s, &c2);
        vals[2 * m] = kvw * c2;
        vals[2 * m + 1] = kvw * s;
    }
    vals[8] = pw;

#pragma unroll
    for (int j = 0; j < 9; j++) {
        float x = vals[j];
#pragma unroll
        for (int d = 16; d > 0; d >>= 1) x += __shfl_xor_sync(0xffffffffu, x, d);
        vals[j] = x;
    }
    if (lane == 0) {
#pragma unroll
        for (int j = 0; j < 8; j++) {
            int m = j >> 1, ri = j & 1;
            size_t ch = (((size_t)bk * HH + h) * MM + m) * 2 + ri;
            g_csum[ch * NCH2 + chunk] = vals[j];
        }
        if (h == 0) g_dsum[(size_t)bk * NCH2 + chunk] = vals[8];
    }
}

// ---------------- exclusive scan of chunk sums (phase 2) ----------------
__global__ void scanoff_kernel() {
    int idx = blockIdx.x * 256 + threadIdx.x;
    const int NRI = BB * KK * HH * MM * 2;
    if (idx < NRI) {
        float run = 0.0f;
#pragma unroll 8
        for (int c = 0; c < NCH2; c++) {
            float x = g_csum[(size_t)idx * NCH2 + c];
            g_coff[(size_t)idx * NCH2 + c] = run;
            run += x;
        }
    } else if (idx < NRI + BB * KK) {
        int d = idx - NRI;
        float run = 0.0f;
#pragma unroll 8
        for (int c = 0; c < NCH2; c++) {
            float x = g_dsum[(size_t)d * NCH2 + c];
            g_doff[(size_t)d * NCH2 + c] = run;
            run += x;
        }
    }
}

// ---------------- fused in-chunk scan + q-combine (h-split, coalesced) ----
__global__ void __launch_bounds__(256) phase3_kernel(const float* __restrict__ tscale,
                                                     const float* __restrict__ nscale) {
    __shared__ float tile[8][32][33];
    int bz = blockIdx.z;            // b * 4 + hq
    int b = bz >> 2, hq = bz & 3;
    int k = blockIdx.y;
    int w = threadIdx.x >> 5, lane = threadIdx.x & 31;
    int chunk = blockIdx.x * 8 + w;
    int t = chunk * LC2 + lane;
    int bk = b * KK + k;

    float pw = g_pw[(size_t)bk * LL + t];
    float x = pw;
#pragma unroll
    for (int d = 1; d < 32; d <<= 1) {
        float n = __shfl_up_sync(0xffffffffu, x, d);
        if (lane >= d) x += n;
    }
    float den = g_doff[(size_t)bk * NCH2 + chunk] + x;
    float invden = 1.0f / fmaxf(den, 1e-4f);

    int kq = k >> 1;
    const float* qbase = g_qt + ((size_t)(b * 3072 + kq * 512)) * LL + t;
    float ts = tscale[k];
    size_t kvbase = ((size_t)bk * HH) * LL + t;
    size_t chb_base = ((size_t)bk * HH) * MM;
    int thb_base = (k * HH) * MM;

    const int h0 = hq * 16;
    for (int hl = 0; hl < 16; hl++) {
        int h = h0 + hl;
        float kv = g_kval[kvbase + (size_t)h * LL];
        float kvw = kv * pw;
        float tanhv = tanhf(ts * kv);
        const float* qp = qbase + (size_t)(h * 8) * LL;
        float qv[8];
#pragma unroll
        for (int j = 0; j < 8; j++) qv[j] = qp[(size_t)j * LL];
        int thb = thb_base + h * MM;
        size_t chb = chb_base + (size_t)h * MM;
        float v[8];
#pragma unroll
        for (int m = 0; m < MM; m++) {
            float s, c2;
            __sincosf(tanhv * g_theta[thb + m], &s, &c2);
            v[2 * m] = kvw * c2;
            v[2 * m + 1] = kvw * s;
        }
#pragma unroll
        for (int j = 0; j < 8; j++) {
            float y = v[j];
#pragma unroll
            for (int d = 1; d < 32; d <<= 1) {
                float n = __shfl_up_sync(0xffffffffu, y, d);
                if (lane >= d) y += n;
            }
            v[j] = y;
        }
        float accre = 0.0f, accim = 0.0f;
#pragma unroll
        for (int m = 0; m < MM; m++) {
            float offre = g_coff[((chb + m) * 2 + 0) * NCH2 + chunk];
            float offim = g_coff[((chb + m) * 2 + 1) * NCH2 + chunk];
            float sre = (offre + v[2 * m]) * invden;
            float sim = (offim + v[2 * m + 1]) * invden;
            float wg = g_wint[thb + m];
            float qr = qv[2 * m], qi = qv[2 * m + 1];
            accre += (sre * qr + sim * qi) * wg;
            accim += (sim * qr - sre * qi) * wg;
        }
        float ns = nscale[k * HH + h];
        tile[w][lane][hl] = accre * ns;
        tile[w][lane][16 + hl] = accim * ns;
    }
    __syncwarp();
    size_t Abase = ((size_t)k * BL + (size_t)b * LL + (size_t)chunk * LC2) * 128;
    int hh = (lane < 16) ? (h0 + lane) : (64 + h0 + (lane - 16));
    for (int r = 0; r < 32; r++) {
        g_Ah[Abase + (size_t)r * 128 + hh] = __float2half(tile[w][r][lane]);
    }
}

// ---------------- gate/highway/silu epilogue (half out: feeds out GEMM) ---
__global__ void combine2_kernel(const float* __restrict__ gate_b,
                                const float* __restrict__ hscale) {
    int idx = blockIdx.x * 256 + threadIdx.x;
    if (idx >= BL * 2304) return;
    int row = idx / 2304, n = idx % 2304;
    int k = n / EXPn, e = n % EXPn;
    size_t sb = ((size_t)k * BL + row) * DSWn;
    float sv = g_yspec[sb + e];
    float sg = g_yspec[sb + EXPn + e];
    size_t db = (size_t)row * 4608 + (size_t)k * DSWn;
    float dv = g_ydir[db + e];
    float dg = g_ydir[db + EXPn + e];
    float gate = 1.0f / (1.0f + __expf(-(g_gatelin[(size_t)row * KK + k] + gate_b[k])));
    float hs = hscale[k];
    float val = sv * gate + dv * hs;
    float gt = sg * gate + dg * hs;
    g_yfinh[(size_t)row * 2304 + n] = __float2half(val * gt / (1.0f + __expf(-gt)));
}

// ---------------- host launcher (R13 stream graph, fp16 GEMMs) ------------
extern "C" void kernel_launch(void* const* d_in, const int* in_sizes, int n_in,
                              void* d_out, int out_size) {
    const float* x = (const float*)d_in[0];
    const float* W_mem = (const float*)d_in[1];
    const float* conv_k = (const float*)d_in[2];
    const float* W_q = (const float*)d_in[3];
    const float* theta_raw = (const float*)d_in[4];
    const float* decay = (const float*)d_in[5];
    const float* sscale = (const float*)d_in[6];
    const float* tscale = (const float*)d_in[7];
    const float* W_re = (const float*)d_in[8];
    const float* W_im = (const float*)d_in[9];
    const float* nscale = (const float*)d_in[10];
    const float* gate_W = (const float*)d_in[11];
    const float* gate_b = (const float*)d_in[12];
    const float* skip_down = (const float*)d_in[13];
    const float* skip_up = (const float*)d_in[14];
    const float* hscale = (const float*)d_in[15];
    const float* out_W = (const float*)d_in[16];

    float *z0, *q, *lat, *ydir, *yspec;
    __half *xrh, *wqt, *wmemt, *sdt, *sut, *owt, *wcatt, *Ah, *lath, *yfinh;
    cudaGetSymbolAddress((void**)&z0, g_z0);
    cudaGetSymbolAddress((void**)&q, g_q);
    cudaGetSymbolAddress((void**)&lat, g_lat);
    cudaGetSymbolAddress((void**)&ydir, g_ydir);
    cudaGetSymbolAddress((void**)&yspec, g_yspec);
    cudaGetSymbolAddress((void**)&xrh, g_xrh);
    cudaGetSymbolAddress((void**)&wqt, g_wqt);
    cudaGetSymbolAddress((void**)&wmemt, g_wmemt);
    cudaGetSymbolAddress((void**)&sdt, g_sdt);
    cudaGetSymbolAddress((void**)&sut, g_sut);
    cudaGetSymbolAddress((void**)&owt, g_owt);
    cudaGetSymbolAddress((void**)&wcatt, g_wcatt);
    cudaGetSymbolAddress((void**)&Ah, g_Ah);
    cudaGetSymbolAddress((void**)&lath, g_lath);
    cudaGetSymbolAddress((void**)&yfinh, g_yfinh);

    static cudaStream_t s1 = 0, s2 = 0, s3 = 0;
    static cudaEvent_t eR1 = 0, eR2 = 0, eQ2 = 0, eQT = 0, eDir = 0;
    static int init_done = 0;
    if (!init_done) {
        cudaFuncSetAttribute(hgemm_kernel, cudaFuncAttributeMaxDynamicSharedMemorySize,
                             SMEM_BYTES);
        cudaStreamCreateWithFlags(&s1, cudaStreamNonBlocking);
        cudaStreamCreateWithFlags(&s2, cudaStreamNonBlocking);
        cudaStreamCreateWithFlags(&s3, cudaStreamNonBlocking);
        cudaEventCreateWithFlags(&eR1, cudaEventDisableTiming);
        cudaEventCreateWithFlags(&eR2, cudaEventDisableTiming);
        cudaEventCreateWithFlags(&eQ2, cudaEventDisableTiming);
        cudaEventCreateWithFlags(&eQT, cudaEventDisableTiming);
        cudaEventCreateWithFlags(&eDir, cudaEventDisableTiming);
        init_done = 1;
    }

    // ---- prologue: x + Wq^T first so q halves start ASAP ----
    hx_kernel<<<(BL * DD / 4 + 255) / 256, 256>>>(x);
    htrans_kernel<<<dim3(96, 24), dim3(32, 8)>>>(W_q, wqt, DD, 3072);
    cudaEventRecord(eR1, 0);
    cudaStreamWaitEvent(s1, eR1, 0);
    cudaStreamWaitEvent(s3, eR1, 0);

    // ---- s1/s3: q GEMM column halves; then full qt transpose on s1 ----
    hgemm_kernel<<<dim3(12, 32, 1), 256, SMEM_BYTES, s1>>>(
        xrh, wqt, q, 1536, 3072, DD, 0, 0, 0);
    hgemm_kernel<<<dim3(12, 32, 1), 256, SMEM_BYTES, s3>>>(
        xrh, wqt + (size_t)1536 * DD, q + 1536, 1536, 3072, DD, 0, 0, 0);
    cudaEventRecord(eQ2, s3);
    cudaStreamWaitEvent(s1, eQ2, 0);
    qt_kernel<<<dim3(96, 128), dim3(32, 8), 0, s1>>>();
    cudaEventRecord(eQT, s1);

    // ---- rest of prologue on main stream ----
    htrans_kernel<<<dim3(25, 24), dim3(32, 8)>>>(W_mem, wmemt, DD, ZC);
    htrans_kernel<<<dim3(6, 24), dim3(32, 8)>>>(skip_down, sdt, DD, LATn);
    htrans_kernel<<<dim3(144, 6), dim3(32, 8)>>>(skip_up, sut, LATn, 4608);
    htrans_kernel<<<dim3(24, 72), dim3(32, 8)>>>(out_W, owt, 2304, DD);
    wcatt_kernel<<<dim3(12, 4, KK), dim3(32, 8)>>>(W_re, W_im);
    precompute_kernel<<<3, 256>>>(theta_raw, decay);
    cudaEventRecord(eR2, 0);
    cudaStreamWaitEvent(s2, eR2, 0);

    // ---- side stream s2: skip path + gate ----
    hgemm_kernel<<<dim3(2, 32, 1), 256, SMEM_BYTES, s2>>>(
        xrh, sdt, lat, LATn, LATn, DD, 0, 0, 0);
    lath_kernel<<<(BL * LATn / 4 + 255) / 256, 256, 0, s2>>>();
    hgemm_kernel<<<dim3(36, 32, 1), 256, SMEM_BYTES, s2>>>(
        lath, sut, ydir, 4608, 4608, LATn, 0, 0, 0);
    gate_kernel<<<BL / 8, 256, 0, s2>>>(x, gate_W);
    cudaEventRecord(eDir, s2);

    // ---- main critical chain ----
    hgemm_kernel<<<dim3(7, 32, 1), 256, SMEM_BYTES>>>(
        xrh, wmemt, z0, ZC, ZC, DD, 0, 0, 0);
    conv_kernel<<<dim3(25, 64, BB), dim3(32, 8)>>>(conv_k, sscale);
    chunksum_kernel<<<dim3(8, HH, BB * KK), 256>>>(tscale);
    scanoff_kernel<<<(BB * KK * HH * MM * 2 + BB * KK + 255) / 256, 256>>>();
    cudaStreamWaitEvent(0, eQT, 0);
    phase3_kernel<<<dim3(8, KK, BB * 4), 256>>>(tscale, nscale);

    // yspec[k] = A_k (4096x128) @ wcatt_k^T (384x128)^T, batched over k
    hgemm_kernel<<<dim3(3, 32, KK), 256, SMEM_BYTES>>>(
        Ah, wcatt, yspec, DSWn, DSWn, 128,
        (size_t)BL * 128, (size_t)DSWn * 128, (size_t)BL * DSWn);

    cudaStreamWaitEvent(0, eDir, 0);
    combine2_kernel<<<((size_t)BL * 2304 + 255) / 256, 256>>>(gate_b, hscale);

    // out = yfin (4096x2304) @ owt^T (768x2304)^T
    hgemm_kernel<<<dim3(6, 32, 1), 256, SMEM_BYTES>>>(
        yfinh, owt, (float*)d_out, DD, DD, 2304, 0, 0, 0);
}